// round 1
// baseline (speedup 1.0000x reference)
#include <cuda_runtime.h>
#include <cstdint>
#include <math.h>

#define NT 8192
#define DM 2048
#define DH 2048
#define NE 16

#define BM 128
#define BN 128
#define BK 16
#define KTILES (DM / BK)   // 128

// Device scratch (no allocations allowed)
__device__ int   g_count[NE];
__device__ int   g_list[NE][NT];
__device__ float g_gate[NE][NT];

// ---------------------------------------------------------------------------
// Kernel 0: zero output + counters
// ---------------------------------------------------------------------------
__global__ void zero_kernel(float4* __restrict__ out, int n4) {
    if (blockIdx.x == 0 && threadIdx.x < NE) g_count[threadIdx.x] = 0;
    int idx = blockIdx.x * blockDim.x + threadIdx.x;
    int stride = gridDim.x * blockDim.x;
    for (int i = idx; i < n4; i += stride)
        out[i] = make_float4(0.f, 0.f, 0.f, 0.f);
}

// ---------------------------------------------------------------------------
// Kernel 1: router — warp per token: 16 dots, top-2, softmax, bucket insert
// ---------------------------------------------------------------------------
__global__ void router_kernel(const float* __restrict__ x,
                              const float* __restrict__ rw) {
    int token = (blockIdx.x * blockDim.x + threadIdx.x) >> 5;
    int lane  = threadIdx.x & 31;
    if (token >= NT) return;

    const float* xr = x + (size_t)token * DM;
    float acc[NE];
#pragma unroll
    for (int e = 0; e < NE; e++) acc[e] = 0.f;

    for (int i = lane; i < DM; i += 32) {
        float xv = xr[i];
#pragma unroll
        for (int e = 0; e < NE; e++)
            acc[e] = fmaf(xv, rw[e * DM + i], acc[e]);
    }
#pragma unroll
    for (int off = 16; off > 0; off >>= 1) {
#pragma unroll
        for (int e = 0; e < NE; e++)
            acc[e] += __shfl_xor_sync(0xFFFFFFFFu, acc[e], off);
    }

    if (lane == 0) {
        // top-1 (earliest on ties, matching jax top_k)
        int i1 = 0; float v1 = acc[0];
#pragma unroll
        for (int e = 1; e < NE; e++)
            if (acc[e] > v1) { v1 = acc[e]; i1 = e; }
        // top-2
        int i2 = -1; float v2 = -3.402823466e38f;
#pragma unroll
        for (int e = 0; e < NE; e++)
            if (e != i1 && acc[e] > v2) { v2 = acc[e]; i2 = e; }

        float t  = expf(v2 - v1);          // v1 >= v2, numerically safe
        float g1 = 1.f / (1.f + t);
        float g2 = t * g1;

        int p1 = atomicAdd(&g_count[i1], 1);
        g_list[i1][p1] = token; g_gate[i1][p1] = g1;
        int p2 = atomicAdd(&g_count[i2], 1);
        g_list[i2][p2] = token; g_gate[i2][p2] = g2;
    }
}

// ---------------------------------------------------------------------------
// Kernel 2: per-expert gathered GEMM, tf32 mma.sync, gate-scaled atomic epilogue
// ---------------------------------------------------------------------------
__device__ __forceinline__ unsigned f2tf32(float f) {
    unsigned r;
    asm("cvt.rna.tf32.f32 %0, %1;" : "=r"(r) : "f"(f));
    return r;
}

__device__ __forceinline__ void mma_tf32(float& c0, float& c1, float& c2, float& c3,
                                         unsigned a0, unsigned a1, unsigned a2, unsigned a3,
                                         unsigned b0, unsigned b1) {
    asm volatile(
        "mma.sync.aligned.m16n8k8.row.col.f32.tf32.tf32.f32 "
        "{%0,%1,%2,%3}, {%4,%5,%6,%7}, {%8,%9}, {%0,%1,%2,%3};"
        : "+f"(c0), "+f"(c1), "+f"(c2), "+f"(c3)
        : "r"(a0), "r"(a1), "r"(a2), "r"(a3), "r"(b0), "r"(b1));
}

__global__ void __launch_bounds__(256, 2)
moe_gemm_kernel(const float* __restrict__ x,
                const float* __restrict__ w,
                float* __restrict__ out) {
    const int e   = blockIdx.z;
    const int cnt = g_count[e];
    const int m0  = blockIdx.y * BM;
    if (m0 >= cnt) return;
    const int n0  = blockIdx.x * BN;

    const float* W = w + (size_t)e * DM * DH;   // [K=DM][N=DH]

    __shared__ __align__(16) unsigned As[BM][BK + 4];   // row stride 20
    __shared__ __align__(16) unsigned Bs[BK][BN + 4];   // row stride 132

    const int tid  = threadIdx.x;
    const int lane = tid & 31;
    const int wid  = tid >> 5;
    const int wm   = wid & 3;     // 4 warps along M  -> 32 rows each
    const int wn   = wid >> 2;    // 2 warps along N  -> 64 cols each
    const int grp  = lane >> 2;   // 0..7
    const int tg   = lane & 3;    // 0..3

    // A loads: 2 float4 per thread. v -> row = v>>2, c4 = v&3
    const int ar0 = tid >> 2,          ac0 = (tid & 3) * 4;
    const int ar1 = (tid + 256) >> 2,  ac1 = ac0;        // same c4 pattern
    int gm0 = m0 + ar0, gm1 = m0 + ar1;
    int tok0 = (gm0 < cnt) ? g_list[e][gm0] : 0;
    int tok1 = (gm1 < cnt) ? g_list[e][gm1] : 0;
    const float* xA0 = x + (size_t)tok0 * DM + ac0;
    const float* xA1 = x + (size_t)tok1 * DM + ac1;

    // B loads: 2 float4 per thread. v -> brow = v>>5, bc4 = v&31
    const int br0 = tid >> 5,         bc0 = (tid & 31) * 4;
    const int br1 = (tid + 256) >> 5, bc1 = bc0;
    const float* wB0 = W + (size_t)br0 * DH + n0 + bc0;
    const float* wB1 = W + (size_t)br1 * DH + n0 + bc1;

    float c[2][8][4];
#pragma unroll
    for (int im = 0; im < 2; im++)
#pragma unroll
        for (int in_ = 0; in_ < 8; in_++)
#pragma unroll
            for (int j = 0; j < 4; j++) c[im][in_][j] = 0.f;

    float4 ra0, ra1, rb0, rb1;

    // prologue: kt = 0
    ra0 = *reinterpret_cast<const float4*>(xA0);
    ra1 = *reinterpret_cast<const float4*>(xA1);
    rb0 = *reinterpret_cast<const float4*>(wB0);
    rb1 = *reinterpret_cast<const float4*>(wB1);

    for (int kt = 1; kt <= KTILES; kt++) {
        // store staged tile to smem (tf32-converted)
        {
            uint4 p;
            p.x = f2tf32(ra0.x); p.y = f2tf32(ra0.y); p.z = f2tf32(ra0.z); p.w = f2tf32(ra0.w);
            *reinterpret_cast<uint4*>(&As[ar0][ac0]) = p;
            p.x = f2tf32(ra1.x); p.y = f2tf32(ra1.y); p.z = f2tf32(ra1.z); p.w = f2tf32(ra1.w);
            *reinterpret_cast<uint4*>(&As[ar1][ac1]) = p;
            p.x = f2tf32(rb0.x); p.y = f2tf32(rb0.y); p.z = f2tf32(rb0.z); p.w = f2tf32(rb0.w);
            *reinterpret_cast<uint4*>(&Bs[br0][bc0]) = p;
            p.x = f2tf32(rb1.x); p.y = f2tf32(rb1.y); p.z = f2tf32(rb1.z); p.w = f2tf32(rb1.w);
            *reinterpret_cast<uint4*>(&Bs[br1][bc1]) = p;
        }
        __syncthreads();

        // stage next tile from gmem while computing on smem
        if (kt < KTILES) {
            int k0 = kt * BK;
            ra0 = *reinterpret_cast<const float4*>(xA0 + k0);
            ra1 = *reinterpret_cast<const float4*>(xA1 + k0);
            rb0 = *reinterpret_cast<const float4*>(wB0 + (size_t)k0 * DH);
            rb1 = *reinterpret_cast<const float4*>(wB1 + (size_t)k0 * DH);
        }

#pragma unroll
        for (int ks = 0; ks < BK; ks += 8) {
            unsigned a[2][4];
#pragma unroll
            for (int im = 0; im < 2; im++) {
                int mb = wm * 32 + im * 16;
                a[im][0] = As[mb + grp    ][ks + tg    ];
                a[im][1] = As[mb + grp + 8][ks + tg    ];
                a[im][2] = As[mb + grp    ][ks + tg + 4];
                a[im][3] = As[mb + grp + 8][ks + tg + 4];
            }
            unsigned b[8][2];
#pragma unroll
            for (int in_ = 0; in_ < 8; in_++) {
                int nb = wn * 64 + in_ * 8;
                b[in_][0] = Bs[ks + tg    ][nb + grp];
                b[in_][1] = Bs[ks + tg + 4][nb + grp];
            }
#pragma unroll
            for (int im = 0; im < 2; im++)
#pragma unroll
                for (int in_ = 0; in_ < 8; in_++)
                    mma_tf32(c[im][in_][0], c[im][in_][1], c[im][in_][2], c[im][in_][3],
                             a[im][0], a[im][1], a[im][2], a[im][3],
                             b[in_][0], b[in_][1]);
        }
        __syncthreads();
    }

    // epilogue: gate-scale + atomic scatter-add into out (exactly 2 adds/elem)
#pragma unroll
    for (int im = 0; im < 2; im++) {
#pragma unroll
        for (int half = 0; half < 2; half++) {
            int gm = m0 + wm * 32 + im * 16 + grp + half * 8;
            if (gm >= cnt) continue;
            int tok   = g_list[e][gm];
            float gt  = g_gate[e][gm];
            float* orow = out + (size_t)tok * DH + n0;
#pragma unroll
            for (int in_ = 0; in_ < 8; in_++) {
                int col = wn * 64 + in_ * 8 + 2 * tg;
                atomicAdd(orow + col,     gt * c[im][in_][half * 2 + 0]);
                atomicAdd(orow + col + 1, gt * c[im][in_][half * 2 + 1]);
            }
        }
    }
}

// ---------------------------------------------------------------------------
extern "C" void kernel_launch(void* const* d_in, const int* in_sizes, int n_in,
                              void* d_out, int out_size) {
    const float* x  = (const float*)d_in[0];   // [NT, DM]
    const float* rw = (const float*)d_in[1];   // [NE, DM]
    const float* ew = (const float*)d_in[2];   // [NE, DM, DH]
    float* out = (float*)d_out;                // [NT, DH]

    zero_kernel<<<2048, 256>>>((float4*)out, NT * DH / 4);
    router_kernel<<<NT / 8, 256>>>(x, rw);

    dim3 grid(DH / BN, NT / BM, NE);           // (16, 64, 16)
    moe_gemm_kernel<<<grid, 256>>>(x, ew, out);
}

// round 4
// speedup vs baseline: 1.2130x; 1.2130x over previous
#include <cuda_runtime.h>
#include <cstdint>
#include <math.h>

#define NT 8192
#define DM 2048
#define DH 2048
#define NE 16

#define BM 128
#define BN 128
#define BK 16
#define KTILES (DM / BK)   // 128
#define STAGES 4

#define ASTRIDE 20         // floats per A row in smem (conflict-free for mma pattern)
#define BSTRIDE 136        // floats per B row in smem (conflict-free)
#define A_STAGE (BM * ASTRIDE)   // 2560 floats
#define B_STAGE (BK * BSTRIDE)   // 2176 floats
#define SMEM_BYTES (STAGES * (A_STAGE + B_STAGE) * 4)   // 75776 B

// Device scratch (allocation-free)
__device__ int   g_count[NE];
__device__ int   g_list[NE][NT];                    // token*2 + slot
__device__ float g_gate[NE][NT];
__device__ float g_scratch[(size_t)NT * 2 * DH];    // 128 MB: per-(token,slot) rows

// ---------------------------------------------------------------------------
__global__ void zero_counters() {
    if (threadIdx.x < NE) g_count[threadIdx.x] = 0;
}

// ---------------------------------------------------------------------------
// Router: warp per token, 16 dots, top-2, softmax, bucket insert (tagged slot)
// ---------------------------------------------------------------------------
__global__ void router_kernel(const float* __restrict__ x,
                              const float* __restrict__ rw) {
    int token = (blockIdx.x * blockDim.x + threadIdx.x) >> 5;
    int lane  = threadIdx.x & 31;
    if (token >= NT) return;

    const float* xr = x + (size_t)token * DM;
    float acc[NE];
#pragma unroll
    for (int e = 0; e < NE; e++) acc[e] = 0.f;

    for (int i = lane; i < DM; i += 32) {
        float xv = xr[i];
#pragma unroll
        for (int e = 0; e < NE; e++)
            acc[e] = fmaf(xv, rw[e * DM + i], acc[e]);
    }
#pragma unroll
    for (int off = 16; off > 0; off >>= 1) {
#pragma unroll
        for (int e = 0; e < NE; e++)
            acc[e] += __shfl_xor_sync(0xFFFFFFFFu, acc[e], off);
    }

    if (lane == 0) {
        int i1 = 0; float v1 = acc[0];
#pragma unroll
        for (int e = 1; e < NE; e++)
            if (acc[e] > v1) { v1 = acc[e]; i1 = e; }
        int i2 = -1; float v2 = -3.402823466e38f;
#pragma unroll
        for (int e = 0; e < NE; e++)
            if (e != i1 && acc[e] > v2) { v2 = acc[e]; i2 = e; }

        float t  = expf(v2 - v1);
        float g1 = 1.f / (1.f + t);
        float g2 = t * g1;

        int p1 = atomicAdd(&g_count[i1], 1);
        g_list[i1][p1] = token * 2 + 0; g_gate[i1][p1] = g1;
        int p2 = atomicAdd(&g_count[i2], 1);
        g_list[i2][p2] = token * 2 + 1; g_gate[i2][p2] = g2;
    }
}

// ---------------------------------------------------------------------------
// tf32 helpers
// ---------------------------------------------------------------------------
__device__ __forceinline__ unsigned f2tf32(float f) {
    unsigned r;
    asm("cvt.rna.tf32.f32 %0, %1;" : "=r"(r) : "f"(f));
    return r;
}

__device__ __forceinline__ void mma_tf32(float& c0, float& c1, float& c2, float& c3,
                                         unsigned a0, unsigned a1, unsigned a2, unsigned a3,
                                         unsigned b0, unsigned b1) {
    asm volatile(
        "mma.sync.aligned.m16n8k8.row.col.f32.tf32.tf32.f32 "
        "{%0,%1,%2,%3}, {%4,%5,%6,%7}, {%8,%9}, {%0,%1,%2,%3};"
        : "+f"(c0), "+f"(c1), "+f"(c2), "+f"(c3)
        : "r"(a0), "r"(a1), "r"(a2), "r"(a3), "r"(b0), "r"(b1));
}

#define CP_ASYNC16(dst, src) \
    asm volatile("cp.async.cg.shared.global [%0], [%1], 16;" :: "r"(dst), "l"(src))
#define CP_COMMIT()  asm volatile("cp.async.commit_group;" ::)
#define CP_WAIT(n)   asm volatile("cp.async.wait_group %0;" :: "n"(n))

// ---------------------------------------------------------------------------
// Gathered per-expert GEMM: 128x128x2048, 4-stage cp.async, 4 warps (64x64 each)
// ---------------------------------------------------------------------------
__global__ void __launch_bounds__(128, 2)
moe_gemm_kernel(const float* __restrict__ x,
                const float* __restrict__ w) {
    extern __shared__ float smem[];
    float* sA = smem;                       // [STAGES][BM][ASTRIDE]
    float* sB = smem + STAGES * A_STAGE;    // [STAGES][BK][BSTRIDE]

    const int e   = blockIdx.z;
    const int cnt = g_count[e];
    const int m0  = blockIdx.y * BM;
    if (m0 >= cnt) return;
    const int n0  = blockIdx.x * BN;
    const float* W = w + (size_t)e * DM * DH;    // [K=DM][N=DH]

    const int tid  = threadIdx.x;
    const int lane = tid & 31;
    const int wid  = tid >> 5;
    const int wm   = wid & 1;     // 2 warps along M (64 rows each)
    const int wn   = wid >> 1;    // 2 warps along N (64 cols each)
    const int grp  = lane >> 2;
    const int tg   = lane & 3;

    // Per-thread cp.async source pointers / smem byte offsets (const over kt)
    const float* aSrc[4]; unsigned aOff[4];
    const float* bSrc[4]; unsigned bOff[4];
#pragma unroll
    for (int i = 0; i < 4; i++) {
        int v   = tid + i * 128;
        int row = v >> 2, c4 = v & 3;
        int gm  = m0 + row;
        int tok = g_list[e][gm < cnt ? gm : cnt - 1] >> 1;
        aSrc[i] = x + (size_t)tok * DM + c4 * 4;
        aOff[i] = (unsigned)(row * ASTRIDE + c4 * 4) * 4u;
        int brow = v >> 5, bc4 = v & 31;
        bSrc[i] = W + (size_t)brow * DH + n0 + bc4 * 4;
        bOff[i] = (unsigned)(brow * BSTRIDE + bc4 * 4) * 4u;
    }

    const unsigned sAb = (unsigned)__cvta_generic_to_shared(sA);
    const unsigned sBb = (unsigned)__cvta_generic_to_shared(sB);

#define ISSUE_STAGE(s, kt)                                            \
    do {                                                              \
        unsigned ab = sAb + (unsigned)(s) * (A_STAGE * 4);            \
        unsigned bb = sBb + (unsigned)(s) * (B_STAGE * 4);            \
        _Pragma("unroll")                                             \
        for (int i = 0; i < 4; i++)                                   \
            CP_ASYNC16(ab + aOff[i], aSrc[i] + (kt) * BK);            \
        _Pragma("unroll")                                             \
        for (int i = 0; i < 4; i++)                                   \
            CP_ASYNC16(bb + bOff[i], bSrc[i] + (size_t)(kt) * BK * DH); \
        CP_COMMIT();                                                  \
    } while (0)

#pragma unroll
    for (int s = 0; s < STAGES - 1; s++) ISSUE_STAGE(s, s);

    float c[4][8][4];
#pragma unroll
    for (int im = 0; im < 4; im++)
#pragma unroll
        for (int in_ = 0; in_ < 8; in_++)
#pragma unroll
            for (int j = 0; j < 4; j++) c[im][in_][j] = 0.f;

    for (int kt = 0; kt < KTILES; kt++) {
        CP_WAIT(STAGES - 2);
        __syncthreads();

        if (kt + STAGES - 1 < KTILES)
            ISSUE_STAGE((kt + STAGES - 1) % STAGES, kt + STAGES - 1);

        const float* As = sA + (kt % STAGES) * A_STAGE;
        const float* Bs = sB + (kt % STAGES) * B_STAGE;

#pragma unroll
        for (int ks = 0; ks < BK; ks += 8) {
            unsigned a[4][4];
#pragma unroll
            for (int im = 0; im < 4; im++) {
                int mb = wm * 64 + im * 16;
                a[im][0] = f2tf32(As[(mb + grp    ) * ASTRIDE + ks + tg    ]);
                a[im][1] = f2tf32(As[(mb + grp + 8) * ASTRIDE + ks + tg    ]);
                a[im][2] = f2tf32(As[(mb + grp    ) * ASTRIDE + ks + tg + 4]);
                a[im][3] = f2tf32(As[(mb + grp + 8) * ASTRIDE + ks + tg + 4]);
            }
            unsigned b[8][2];
#pragma unroll
            for (int in_ = 0; in_ < 8; in_++) {
                int nb = wn * 64 + in_ * 8;
                b[in_][0] = f2tf32(Bs[(ks + tg    ) * BSTRIDE + nb + grp]);
                b[in_][1] = f2tf32(Bs[(ks + tg + 4) * BSTRIDE + nb + grp]);
            }
#pragma unroll
            for (int im = 0; im < 4; im++)
#pragma unroll
                for (int in_ = 0; in_ < 8; in_++)
                    mma_tf32(c[im][in_][0], c[im][in_][1], c[im][in_][2], c[im][in_][3],
                             a[im][0], a[im][1], a[im][2], a[im][3],
                             b[in_][0], b[in_][1]);
        }
        // no trailing barrier needed: next-iter top barrier orders compute(kt)
        // before any cp.async overwrites stage kt%STAGES
    }

    // Epilogue: gate-scale, plain STG.64 into disjoint (token,slot) scratch rows
#pragma unroll
    for (int im = 0; im < 4; im++) {
#pragma unroll
        for (int half = 0; half < 2; half++) {
            int gm = m0 + wm * 64 + im * 16 + grp + half * 8;
            if (gm >= cnt) continue;
            int   sl = g_list[e][gm];
            float gt = g_gate[e][gm];
            float* orow = g_scratch + (size_t)sl * DH + n0 + wn * 64;
#pragma unroll
            for (int in_ = 0; in_ < 8; in_++) {
                int col = in_ * 8 + 2 * tg;
                float2 v = make_float2(gt * c[im][in_][half * 2 + 0],
                                       gt * c[im][in_][half * 2 + 1]);
                *reinterpret_cast<float2*>(orow + col) = v;
            }
        }
    }
#undef ISSUE_STAGE
}

// ---------------------------------------------------------------------------
// Combine: out[t] = scratch[2t] + scratch[2t+1]
// ---------------------------------------------------------------------------
__global__ void combine_kernel(float4* __restrict__ out) {
    const int C = DH / 4;
    int i = blockIdx.x * blockDim.x + threadIdx.x;   // < NT*DH/4
    int t = i / C, col = i - t * C;
    const float4* s = reinterpret_cast<const float4*>(g_scratch);
    float4 a = s[(size_t)(2 * t    ) * C + col];
    float4 b = s[(size_t)(2 * t + 1) * C + col];
    out[i] = make_float4(a.x + b.x, a.y + b.y, a.z + b.z, a.w + b.w);
}

// ---------------------------------------------------------------------------
extern "C" void kernel_launch(void* const* d_in, const int* in_sizes, int n_in,
                              void* d_out, int out_size) {
    const float* x  = (const float*)d_in[0];   // [NT, DM]
    const float* rw = (const float*)d_in[1];   // [NE, DM]
    const float* ew = (const float*)d_in[2];   // [NE, DM, DH]
    float* out = (float*)d_out;                // [NT, DH]

    cudaFuncSetAttribute(moe_gemm_kernel,
                         cudaFuncAttributeMaxDynamicSharedMemorySize, SMEM_BYTES);

    zero_counters<<<1, 32>>>();
    router_kernel<<<NT / 8, 256>>>(x, rw);

    dim3 grid(DH / BN, NT / BM, NE);           // (16, 64, 16), early-exit on cnt
    moe_gemm_kernel<<<grid, 128, SMEM_BYTES>>>(x, ew);

    combine_kernel<<<(NT * DH / 4) / 256, 256>>>((float4*)out);
}